// round 6
// baseline (speedup 1.0000x reference)
#include <cuda_runtime.h>

// Problem constants (shapes fixed by the dataset): B=8192, S=4096.
#define MAX_B 8192
#define THREADS 256

#define LOG2E 1.4426950408889634f
#define LN2   0.6931471805599453f

__device__ float g_partial[MAX_B];
__device__ unsigned int g_done = 0;

__device__ __forceinline__ float ex2f(float x) {
    float y; asm("ex2.approx.ftz.f32 %0, %1;" : "=f"(y) : "f"(x)); return y;
}
__device__ __forceinline__ float lg2f(float x) {
    float y; asm("lg2.approx.ftz.f32 %0, %1;" : "=f"(y) : "f"(x)); return y;
}
__device__ __forceinline__ float rcpf(float x) {
    float y; asm("rcp.approx.ftz.f32 %0, %1;" : "=f"(y) : "f"(x)); return y;
}

// Per-element focal term in log2 domain (missing the final *ln2 scale):
//   t   = d * log2e
//   om  = sigmoid(d)        = 1 / (1 + 2^-t)
//   sp2 = softplus(d)/ln2   = lg2(1 + 2^t)
//   fl2 = om^2 * sp2        (true fl = fl2 * ln2)
__device__ __forceinline__ float focal2(float t) {
    const float ep  = ex2f(t);
    const float em  = ex2f(-t);
    const float om  = rcpf(1.0f + em);
    const float sp2 = lg2f(1.0f + ep);
    return om * om * sp2;
}

// One CTA per row; 256 threads x 16 elements via 4x (float4 + int4).
// mask values are exactly {0,1}; head/tail exclusion handled by a one-time
// per-row correction on thread 0 instead of per-element compares.
__global__ void __launch_bounds__(THREADS)
focal_fused_kernel(const float* __restrict__ scores,
                   const int* __restrict__ head,
                   const int* __restrict__ tail,
                   const int* __restrict__ mask,
                   float* __restrict__ out,
                   int S, int B)
{
    const int b   = blockIdx.x;
    const int tid = threadIdx.x;

    const float* __restrict__ srow = scores + (size_t)b * S;
    const int*   __restrict__ mrow = mask   + (size_t)b * S;

    const int hp = head[b];
    const int tp = tail[b];
    const float pos  = __ldg(srow + tp);
    const float pos2 = pos * LOG2E;

    float sum2 = 0.0f;
    int   cnt  = 0;

    // Thread 0 pre-subtracts the head/tail contributions that the mask-only
    // loop below will (wrongly) include.
    if (tid == 0) {
        const int m_tp = __ldg(mrow + tp);
        if (m_tp == 1) {
            // d = 0 exactly: om = 0.5, sp2 = 1  ->  fl2 = 0.25
            sum2 -= 0.25f;
            cnt  -= 1;
        }
        if (hp != tp) {
            const int m_hp = __ldg(mrow + hp);
            if (m_hp == 1) {
                const float s = __ldg(srow + hp);
                const float t = fmaf(s, LOG2E, -pos2);
                sum2 -= focal2(t);
                cnt  -= 1;
            }
        }
    }

    const int n4 = S >> 2;            // 1024 float4s per row
    const int iters = n4 / THREADS;   // 4

    // Front-batch all loads (MLP = 8 per thread).
    float4 sv[4];
    int4   mv[4];
    #pragma unroll
    for (int it = 0; it < iters; ++it) {
        const int c4 = it * THREADS + tid;
        sv[it] = reinterpret_cast<const float4*>(srow)[c4];
        mv[it] = reinterpret_cast<const int4*>(mrow)[c4];
    }

    #pragma unroll
    for (int it = 0; it < iters; ++it) {
        const float sarr[4] = { sv[it].x, sv[it].y, sv[it].z, sv[it].w };
        const int   marr[4] = { mv[it].x, mv[it].y, mv[it].z, mv[it].w };
        #pragma unroll
        for (int j = 0; j < 4; ++j) {
            const float t   = fmaf(sarr[j], LOG2E, -pos2);
            const float fl2 = focal2(t);
            sum2 = fmaf(fl2, (float)marr[j], sum2);   // mask in {0,1}
            cnt += marr[j];
        }
    }

    // Deterministic block reduction: warp shuffles + shared across 8 warps.
    #pragma unroll
    for (int o = 16; o > 0; o >>= 1) {
        sum2 += __shfl_down_sync(0xffffffffu, sum2, o);
        cnt  += __shfl_down_sync(0xffffffffu, cnt, o);
    }
    __shared__ float ssum[8];
    __shared__ int   scnt[8];
    __shared__ bool  is_last;
    const int wid = tid >> 5, lid = tid & 31;
    if (lid == 0) { ssum[wid] = sum2; scnt[wid] = cnt; }
    __syncthreads();
    if (wid == 0) {
        sum2 = (lid < 8) ? ssum[lid] : 0.0f;
        cnt  = (lid < 8) ? scnt[lid] : 0;
        #pragma unroll
        for (int o = 4; o > 0; o >>= 1) {
            sum2 += __shfl_down_sync(0xffffffffu, sum2, o);
            cnt  += __shfl_down_sync(0xffffffffu, cnt, o);
        }
        if (lid == 0) {
            g_partial[b] = (cnt > 0) ? sum2 / (float)cnt : 0.0f;
            __threadfence();
            const unsigned int old = atomicAdd(&g_done, 1u);
            is_last = (old == (unsigned int)(gridDim.x - 1));
        }
    }
    __syncthreads();

    // Last CTA reduces all B partials in fixed order (deterministic).
    if (is_last) {
        float fsum = 0.0f;
        const int nb4 = B >> 2;
        for (int i = tid; i < nb4; i += THREADS) {
            const float4 v = reinterpret_cast<const float4*>(g_partial)[i];
            fsum += (v.x + v.y) + (v.z + v.w);
        }
        #pragma unroll
        for (int o = 16; o > 0; o >>= 1)
            fsum += __shfl_down_sync(0xffffffffu, fsum, o);
        __shared__ float fs[8];
        if (lid == 0) fs[wid] = fsum;
        __syncthreads();
        if (wid == 0) {
            fsum = (lid < 8) ? fs[lid] : 0.0f;
            #pragma unroll
            for (int o = 4; o > 0; o >>= 1)
                fsum += __shfl_down_sync(0xffffffffu, fsum, o);
            if (lid == 0) {
                out[0] = fsum * (LN2 / (float)B);   // fold ln2 scale here
                g_done = 0;                          // reset for graph replay
            }
        }
    }
}

extern "C" void kernel_launch(void* const* d_in, const int* in_sizes, int n_in,
                              void* d_out, int out_size)
{
    // metadata order: scores [B,S] f32, head [B] i32, tail [B] i32, mask [B,S] i32
    const float* scores = (const float*)d_in[0];
    const int*   head   = (const int*)d_in[1];
    const int*   tail   = (const int*)d_in[2];
    const int*   mask   = (const int*)d_in[3];
    float* out = (float*)d_out;

    const int B = in_sizes[1];
    const int S = in_sizes[0] / B;

    focal_fused_kernel<<<B, THREADS>>>(scores, head, tail, mask, out, S, B);
}

// round 8
// speedup vs baseline: 1.5259x; 1.5259x over previous
#include <cuda_runtime.h>

// Problem constants (shapes fixed by the dataset): B=8192, S=4096.
#define MAX_B 8192
#define THREADS 256

#define LOG2E 1.4426950408889634f
#define LN2   0.6931471805599453f

__device__ float g_partial[MAX_B];
__device__ unsigned int g_done = 0;

__device__ __forceinline__ float ex2f(float x) {
    float y; asm("ex2.approx.ftz.f32 %0, %1;" : "=f"(y) : "f"(x)); return y;
}
__device__ __forceinline__ float lg2f(float x) {
    float y; asm("lg2.approx.ftz.f32 %0, %1;" : "=f"(y) : "f"(x)); return y;
}
__device__ __forceinline__ float rcpf(float x) {
    float y; asm("rcp.approx.ftz.f32 %0, %1;" : "=f"(y) : "f"(x)); return y;
}

// Per-element focal term in log2 domain (missing the final *ln2 scale):
//   t   = d * log2e,  ep = 2^t,  u = 1 + ep
//   om  = sigmoid(d)      = ep / u
//   sp2 = softplus(d)/ln2 = lg2(u)
//   fl2 = om^2 * sp2      (true fl = fl2 * ln2)
// 3 MUFU total (ex2, rcp, lg2).
__device__ __forceinline__ float focal2(float t) {
    const float ep  = ex2f(t);
    const float u   = 1.0f + ep;
    const float om  = ep * rcpf(u);
    const float sp2 = lg2f(u);
    return om * om * sp2;
}

// One CTA per row; 256 threads x 16 elements via 4x (float4 + int4).
// mask values are exactly {0,1}; head/tail exclusion handled by a one-time
// per-row correction on thread 0 instead of per-element compares.
__global__ void __launch_bounds__(THREADS)
focal_fused_kernel(const float* __restrict__ scores,
                   const int* __restrict__ head,
                   const int* __restrict__ tail,
                   const int* __restrict__ mask,
                   float* __restrict__ out,
                   int S, int B)
{
    const int b   = blockIdx.x;
    const int tid = threadIdx.x;

    const float* __restrict__ srow = scores + (size_t)b * S;
    const int*   __restrict__ mrow = mask   + (size_t)b * S;

    const int hp = head[b];
    const int tp = tail[b];
    const float pos  = __ldg(srow + tp);
    const float pos2 = pos * LOG2E;

    float sum2 = 0.0f;
    int   cnt  = 0;

    // Thread 0 pre-subtracts the head/tail contributions that the mask-only
    // loop below will (wrongly) include.
    if (tid == 0) {
        const int m_tp = __ldg(mrow + tp);
        if (m_tp == 1) {
            // d = 0 exactly: om = 0.5, sp2 = 1  ->  fl2 = 0.25
            sum2 -= 0.25f;
            cnt  -= 1;
        }
        if (hp != tp) {
            const int m_hp = __ldg(mrow + hp);
            if (m_hp == 1) {
                const float s = __ldg(srow + hp);
                const float t = fmaf(s, LOG2E, -pos2);
                sum2 -= focal2(t);
                cnt  -= 1;
            }
        }
    }

    const int n4 = S >> 2;            // 1024 float4s per row
    const int iters = n4 / THREADS;   // 4

    #pragma unroll
    for (int it = 0; it < iters; ++it) {
        const int c4 = it * THREADS + tid;
        const float4 sv = reinterpret_cast<const float4*>(srow)[c4];
        const int4   mv = reinterpret_cast<const int4*>(mrow)[c4];

        const float sarr[4] = { sv.x, sv.y, sv.z, sv.w };
        const int   marr[4] = { mv.x, mv.y, mv.z, mv.w };
        #pragma unroll
        for (int j = 0; j < 4; ++j) {
            const float t   = fmaf(sarr[j], LOG2E, -pos2);
            const float fl2 = focal2(t);
            // mask in {0,1}: build 0.0f/1.0f weight with one IMAD (no I2F)
            const float mf  = __int_as_float(marr[j] * 0x3f800000);
            sum2 = fmaf(fl2, mf, sum2);
            cnt += marr[j];
        }
    }

    // Deterministic block reduction: warp shuffles + shared across 8 warps.
    #pragma unroll
    for (int o = 16; o > 0; o >>= 1) {
        sum2 += __shfl_down_sync(0xffffffffu, sum2, o);
        cnt  += __shfl_down_sync(0xffffffffu, cnt, o);
    }
    __shared__ float ssum[8];
    __shared__ int   scnt[8];
    __shared__ bool  is_last;
    const int wid = tid >> 5, lid = tid & 31;
    if (lid == 0) { ssum[wid] = sum2; scnt[wid] = cnt; }
    __syncthreads();
    if (wid == 0) {
        sum2 = (lid < 8) ? ssum[lid] : 0.0f;
        cnt  = (lid < 8) ? scnt[lid] : 0;
        #pragma unroll
        for (int o = 4; o > 0; o >>= 1) {
            sum2 += __shfl_down_sync(0xffffffffu, sum2, o);
            cnt  += __shfl_down_sync(0xffffffffu, cnt, o);
        }
        if (lid == 0) {
            g_partial[b] = (cnt > 0) ? sum2 / (float)cnt : 0.0f;
            __threadfence();
            const unsigned int old = atomicAdd(&g_done, 1u);
            is_last = (old == (unsigned int)(gridDim.x - 1));
        }
    }
    __syncthreads();

    // Last CTA reduces all B partials in fixed order (deterministic).
    if (is_last) {
        float fsum = 0.0f;
        const int nb4 = B >> 2;
        for (int i = tid; i < nb4; i += THREADS) {
            const float4 v = reinterpret_cast<const float4*>(g_partial)[i];
            fsum += (v.x + v.y) + (v.z + v.w);
        }
        #pragma unroll
        for (int o = 16; o > 0; o >>= 1)
            fsum += __shfl_down_sync(0xffffffffu, fsum, o);
        __shared__ float fs[8];
        if (lid == 0) fs[wid] = fsum;
        __syncthreads();
        if (wid == 0) {
            fsum = (lid < 8) ? fs[lid] : 0.0f;
            #pragma unroll
            for (int o = 4; o > 0; o >>= 1)
                fsum += __shfl_down_sync(0xffffffffu, fsum, o);
            if (lid == 0) {
                out[0] = fsum * (LN2 / (float)B);   // fold ln2 scale here
                g_done = 0;                          // reset for graph replay
            }
        }
    }
}

extern "C" void kernel_launch(void* const* d_in, const int* in_sizes, int n_in,
                              void* d_out, int out_size)
{
    // metadata order: scores [B,S] f32, head [B] i32, tail [B] i32, mask [B,S] i32
    const float* scores = (const float*)d_in[0];
    const int*   head   = (const int*)d_in[1];
    const int*   tail   = (const int*)d_in[2];
    const int*   mask   = (const int*)d_in[3];
    float* out = (float*)d_out;

    const int B = in_sizes[1];
    const int S = in_sizes[0] / B;

    focal_fused_kernel<<<B, THREADS>>>(scores, head, tail, mask, out, S, B);
}